// round 7
// baseline (speedup 1.0000x reference)
#include <cuda_runtime.h>
#include <cstdint>

// B=16384, N=64, D=64, O=64
// softmax(others@a2 + robot@a1) == softmax(others@a2)  (robot term constant)
// out = elu( diag(1,attn) @ (h@W) )   -- attn folded into the epilogue
// NO smem staging of h: A-fragments are loaded straight from global into
// registers (8x LDG.128 per thread per batch). Dots fused on the fragments.
// One barrier per batch (sdots exchange, double-buffered). B-frags in regs.
// 256-thread CTA: warp w -> rows [16*(w&3),+16) x cols [32*(w>>2),+32).

#define GB 8      // batches per CTA

__device__ __forceinline__ unsigned f2tf32(float x) {
    unsigned r;
    asm("cvt.rna.tf32.f32 %0, %1;" : "=r"(r) : "f"(x));
    return r;
}

__device__ __forceinline__ float elu1(float x) {
    return x > 0.f ? x : (__expf(x) - 1.f);
}

__global__ __launch_bounds__(256, 2)
void gat_fused_kernel(const float* __restrict__ h,
                      const float* __restrict__ W,
                      const float* __restrict__ a,
                      float* __restrict__ out) {
    __shared__ float sdots[2][64];
    __shared__ __align__(16) float sv2[64];

    const int tid  = threadIdx.x;
    const int lane = tid & 31;
    const int warp = tid >> 5;
    const int gid  = lane >> 2;    // 0..7
    const int tig  = lane & 3;     // 0..3
    const int m0   = warp & 3;     // m-tile: rows [16*m0, +16)
    const int cg   = warp >> 2;    // col group: cols [32*cg, +32)

    // ---- B-fragments into registers (once) ----
    // Register A layout (from float4 loads): slab s covers actual k cols
    //   {4s, 4s+1} paired as (k_pos tig -> col 4*tig + (s&1)*... } -- we keep
    // the R6 convention: slab s=2q+odd : k_pos t -> col 16q+4t+2*odd,
    //                                     k_pos t+4 -> col 16q+4t+2*odd+1
    // N-perm: tile nt, local n -> col cg*32+(nt>>1)*16+(n>>1)*4+(nt&1)*2+(n&1)
    unsigned bfr[8][4][2];
    {
#pragma unroll
        for (int s = 0; s < 8; ++s) {
            const int q = s >> 1, odd = s & 1;
            const int kr0 = 16 * q + 4 * tig + 2 * odd;   // k_pos = tig
            const int kr1 = kr0 + 1;                      // k_pos = tig+4
#pragma unroll
            for (int nt = 0; nt < 4; ++nt) {
                int col = cg * 32 + (nt >> 1) * 16 + (gid >> 1) * 4
                        + (nt & 1) * 2 + (gid & 1);
                bfr[s][nt][0] = f2tf32(W[kr0 * 64 + col]);
                bfr[s][nt][1] = f2tf32(W[kr1 * 64 + col]);
            }
        }
    }

    // ---- v2 = W @ a2 (threads 0..63) ----
    if (tid < 64) {
        const float* a2 = a + 64;
        float s = 0.f;
#pragma unroll
        for (int o = 0; o < 64; ++o) s = fmaf(W[tid * 64 + o], a2[o], s);
        sv2[tid] = s;
    }
    __syncthreads();

    const int rA = m0 * 16 + gid;   // this thread's two output rows
    const int rB = rA + 8;
    const size_t base = (size_t)blockIdx.x * GB * 4096;

    // v2 values this thread needs (cols 16q+4tig .. +3), kept in registers
    float4 vv[4];
#pragma unroll
    for (int q = 0; q < 4; ++q)
        vv[q] = *reinterpret_cast<const float4*>(&sv2[16 * q + 4 * tig]);

    for (int g = 0; g < GB; ++g) {
        const float* hb = h + base + (size_t)g * 4096;
        const float4* pA = reinterpret_cast<const float4*>(hb + rA * 64);
        const float4* pB = reinterpret_cast<const float4*>(hb + rB * 64);

        // ---- load A fragments straight from global (8x LDG.128) ----
        float4 fAr[4], fBr[4];
#pragma unroll
        for (int q = 0; q < 4; ++q) {
            fAr[q] = pA[q * 4 + tig];
            fBr[q] = pB[q * 4 + tig];
        }

        // ---- dot partials ----
        float pd0 = 0.f, pd1 = 0.f;
#pragma unroll
        for (int q = 0; q < 4; ++q) {
            pd0 = fmaf(fAr[q].x, vv[q].x, fmaf(fAr[q].y, vv[q].y,
                  fmaf(fAr[q].z, vv[q].z, fmaf(fAr[q].w, vv[q].w, pd0))));
            pd1 = fmaf(fBr[q].x, vv[q].x, fmaf(fBr[q].y, vv[q].y,
                  fmaf(fBr[q].z, vv[q].z, fmaf(fBr[q].w, vv[q].w, pd1))));
        }

        // ---- GEMM (unscaled) ----
        float acc[4][4];
#pragma unroll
        for (int nt = 0; nt < 4; ++nt)
#pragma unroll
            for (int k = 0; k < 4; ++k) acc[nt][k] = 0.f;

#pragma unroll
        for (int q = 0; q < 4; ++q) {
            unsigned e0 = f2tf32(fAr[q].x), e1 = f2tf32(fBr[q].x);
            unsigned e2 = f2tf32(fAr[q].y), e3 = f2tf32(fBr[q].y);
            unsigned o0 = f2tf32(fAr[q].z), o1 = f2tf32(fBr[q].z);
            unsigned o2 = f2tf32(fAr[q].w), o3 = f2tf32(fBr[q].w);
#pragma unroll
            for (int nt = 0; nt < 4; ++nt) {
                asm volatile(
                    "mma.sync.aligned.m16n8k8.row.col.f32.tf32.tf32.f32 "
                    "{%0,%1,%2,%3}, {%4,%5,%6,%7}, {%8,%9}, {%0,%1,%2,%3};"
                    : "+f"(acc[nt][0]), "+f"(acc[nt][1]),
                      "+f"(acc[nt][2]), "+f"(acc[nt][3])
                    : "r"(e0), "r"(e1), "r"(e2), "r"(e3),
                      "r"(bfr[2 * q][nt][0]), "r"(bfr[2 * q][nt][1]));
            }
#pragma unroll
            for (int nt = 0; nt < 4; ++nt) {
                asm volatile(
                    "mma.sync.aligned.m16n8k8.row.col.f32.tf32.tf32.f32 "
                    "{%0,%1,%2,%3}, {%4,%5,%6,%7}, {%8,%9}, {%0,%1,%2,%3};"
                    : "+f"(acc[nt][0]), "+f"(acc[nt][1]),
                      "+f"(acc[nt][2]), "+f"(acc[nt][3])
                    : "r"(o0), "r"(o1), "r"(o2), "r"(o3),
                      "r"(bfr[2 * q + 1][nt][0]), "r"(bfr[2 * q + 1][nt][1]));
            }
        }

        // ---- reduce dots over tig lanes; publish (col-group 0 only) ----
        pd0 += __shfl_xor_sync(0xffffffffu, pd0, 1);
        pd0 += __shfl_xor_sync(0xffffffffu, pd0, 2);
        pd1 += __shfl_xor_sync(0xffffffffu, pd1, 1);
        pd1 += __shfl_xor_sync(0xffffffffu, pd1, 2);
        const int db = g & 1;
        if (cg == 0 && tig == 0) {
            sdots[db][rA] = pd0;
            sdots[db][rB] = pd1;
        }
        __syncthreads();   // sdots[db] complete (double-buffered vs next iter)

        // ---- warp-local softmax over rows 1..63 ----
        float x0 = (lane >= 1) ? sdots[db][lane] : -1e30f;
        float x1 = sdots[db][lane + 32];
        float m = fmaxf(x0, x1);
#pragma unroll
        for (int off = 16; off; off >>= 1)
            m = fmaxf(m, __shfl_xor_sync(0xffffffffu, m, off));
        float e0s = (lane >= 1) ? __expf(x0 - m) : 0.f;
        float e1s = __expf(x1 - m);
        float s = e0s + e1s;
#pragma unroll
        for (int off = 16; off; off >>= 1)
            s += __shfl_xor_sync(0xffffffffu, s, off);
        const float inv = 1.f / s;

        const float fA = (rA == 0) ? 1.f : __expf(pd0 - m) * inv;
        const float fB = __expf(pd1 - m) * inv;   // rB >= 8, never robot

        // ---- epilogue: scale, elu, STG.128 ----
        float* ob = out + base + (size_t)g * 4096;
#pragma unroll
        for (int p = 0; p < 2; ++p) {
            const int col = cg * 32 + p * 16 + tig * 4;
            float4 v0 = make_float4(elu1(acc[2 * p][0] * fA),
                                    elu1(acc[2 * p][1] * fA),
                                    elu1(acc[2 * p + 1][0] * fA),
                                    elu1(acc[2 * p + 1][1] * fA));
            float4 v1 = make_float4(elu1(acc[2 * p][2] * fB),
                                    elu1(acc[2 * p][3] * fB),
                                    elu1(acc[2 * p + 1][2] * fB),
                                    elu1(acc[2 * p + 1][3] * fB));
            *reinterpret_cast<float4*>(ob + rA * 64 + col) = v0;
            *reinterpret_cast<float4*>(ob + rB * 64 + col) = v1;
        }
    }
}

extern "C" void kernel_launch(void* const* d_in, const int* in_sizes, int n_in,
                              void* d_out, int out_size) {
    const float* h = (const float*)d_in[0];   // (16384, 64, 64) f32
    const float* W = (const float*)d_in[1];   // (64, 64) f32
    const float* a = (const float*)d_in[2];   // (128, 1) f32
    float* out = (float*)d_out;               // (16384, 64, 64) f32

    gat_fused_kernel<<<16384 / GB, 256>>>(h, W, a, out);
}

// round 8
// speedup vs baseline: 1.6376x; 1.6376x over previous
#include <cuda_runtime.h>
#include <cuda_fp16.h>
#include <cstdint>

// B=16384, N=64, D=64, O=64
// softmax(others@a2 + robot@a1) == softmax(others@a2)  (robot term constant)
// out = elu( diag(1,attn) @ (h@W) )   -- attn folded into the epilogue
// R6 structure (cp.async double-buffered smem, fused dots, warp-local softmax,
// N-permuted STG.128) with the GEMM in fp16 m16n8k16: half the MMA count,
// half the cvt count, half the B-frag registers. Dots stay fp32-exact.

#define GB 8      // batches per CTA
#define HS 80     // h smem row stride (floats): conflict-free float4 phases

__device__ __forceinline__ unsigned h2u(__half2 h) {
    return *reinterpret_cast<unsigned*>(&h);
}

__device__ __forceinline__ float elu1(float x) {
    return x > 0.f ? x : (__expf(x) - 1.f);
}

__device__ __forceinline__ void cp_async16(uint32_t saddr, const void* gptr) {
    asm volatile("cp.async.cg.shared.global [%0], [%1], 16;\n"
                 :: "r"(saddr), "l"(gptr));
}

__global__ __launch_bounds__(256)
void gat_fused_kernel(const float* __restrict__ h,
                      const float* __restrict__ W,
                      const float* __restrict__ a,
                      float* __restrict__ out) {
    __shared__ float sh[2][64 * HS];            // double-buffered h (fp32)
    __shared__ float sdots[64];
    __shared__ __align__(16) float sv2[64];

    const int tid  = threadIdx.x;
    const int lane = tid & 31;
    const int warp = tid >> 5;
    const int gid  = lane >> 2;    // 0..7
    const int tig  = lane & 3;     // 0..3
    const int m0   = warp & 3;     // m-tile: rows [16*m0, +16)
    const int cg   = warp >> 2;    // col group: cols [32*cg, +32)

    // ---- B-fragments (fp16) into registers, once ----
    // K-perm within slab q (actual cols 16q..16q+15):
    //   actual 16q+4t+0 <-> mma-k 2t   ; 16q+4t+1 <-> mma-k 2t+1
    //   actual 16q+4t+2 <-> mma-k 2t+8 ; 16q+4t+3 <-> mma-k 2t+9
    // N-perm: tile nt, local n -> col cg*32+(nt>>1)*16+(n>>1)*4+(nt&1)*2+(n&1)
    unsigned bfr[4][4][2];
    {
#pragma unroll
        for (int q = 0; q < 4; ++q) {
            const int kr = 16 * q + 4 * tig;
#pragma unroll
            for (int nt = 0; nt < 4; ++nt) {
                int col = cg * 32 + (nt >> 1) * 16 + (gid >> 1) * 4
                        + (nt & 1) * 2 + (gid & 1);
                bfr[q][nt][0] = h2u(__floats2half2_rn(W[kr * 64 + col],
                                                      W[(kr + 1) * 64 + col]));
                bfr[q][nt][1] = h2u(__floats2half2_rn(W[(kr + 2) * 64 + col],
                                                      W[(kr + 3) * 64 + col]));
            }
        }
    }

    // ---- v2 = W @ a2 (threads 0..63) ----
    if (tid < 64) {
        const float* a2 = a + 64;
        float s = 0.f;
#pragma unroll
        for (int o = 0; o < 64; ++o) s = fmaf(W[tid * 64 + o], a2[o], s);
        sv2[tid] = s;
    }

    const size_t base = (size_t)blockIdx.x * GB * 4096;

    // ---- prefetch batch 0 ----
    {
        const float* hb = h + base;
        uint32_t sb = (uint32_t)__cvta_generic_to_shared(&sh[0][0]);
#pragma unroll
        for (int c = tid; c < 1024; c += 256) {
            int row = c >> 4, q = c & 15;
            cp_async16(sb + (row * HS + q * 4) * 4, hb + c * 4);
        }
        asm volatile("cp.async.commit_group;\n");
    }

    const int rA = m0 * 16 + gid;   // this thread's two output rows
    const int rB = rA + 8;

    for (int g = 0; g < GB; ++g) {
        const int buf = g & 1;

        asm volatile("cp.async.wait_group 0;\n");
        __syncthreads();   // buf[g] ready; prev iter's sdots reads done; sv2 ready

        // ---- prefetch batch g+1 ----
        if (g + 1 < GB) {
            const float* hb = h + base + (size_t)(g + 1) * 4096;
            uint32_t sb = (uint32_t)__cvta_generic_to_shared(&sh[buf ^ 1][0]);
#pragma unroll
            for (int c = tid; c < 1024; c += 256) {
                int row = c >> 4, q = c & 15;
                cp_async16(sb + (row * HS + q * 4) * 4, hb + c * 4);
            }
            asm volatile("cp.async.commit_group;\n");
        }

        // ---- GEMM (fp16, unscaled) + fp32 dot partials ----
        float acc[4][4];
#pragma unroll
        for (int nt = 0; nt < 4; ++nt)
#pragma unroll
            for (int k = 0; k < 4; ++k) acc[nt][k] = 0.f;

        float pd0 = 0.f, pd1 = 0.f;
        const float* shb = &sh[buf][0];

#pragma unroll
        for (int q = 0; q < 4; ++q) {
            const int cb = 16 * q + 4 * tig;
            const float4 vA = *reinterpret_cast<const float4*>(&shb[rA * HS + cb]);
            const float4 vB = *reinterpret_cast<const float4*>(&shb[rB * HS + cb]);
            const float4 vv = *reinterpret_cast<const float4*>(&sv2[cb]);

            pd0 = fmaf(vA.x, vv.x, fmaf(vA.y, vv.y,
                  fmaf(vA.z, vv.z, fmaf(vA.w, vv.w, pd0))));
            pd1 = fmaf(vB.x, vv.x, fmaf(vB.y, vv.y,
                  fmaf(vB.z, vv.z, fmaf(vB.w, vv.w, pd1))));

            // A fragments (k16): a0=(rA, k 2t,2t+1)  a1=(rB, same)
            //                    a2=(rA, k 2t+8,2t+9) a3=(rB, same)
            unsigned a0 = h2u(__floats2half2_rn(vA.x, vA.y));
            unsigned a1 = h2u(__floats2half2_rn(vB.x, vB.y));
            unsigned a2 = h2u(__floats2half2_rn(vA.z, vA.w));
            unsigned a3 = h2u(__floats2half2_rn(vB.z, vB.w));
#pragma unroll
            for (int nt = 0; nt < 4; ++nt) {
                asm volatile(
                    "mma.sync.aligned.m16n8k16.row.col.f32.f16.f16.f32 "
                    "{%0,%1,%2,%3}, {%4,%5,%6,%7}, {%8,%9}, {%0,%1,%2,%3};"
                    : "+f"(acc[nt][0]), "+f"(acc[nt][1]),
                      "+f"(acc[nt][2]), "+f"(acc[nt][3])
                    : "r"(a0), "r"(a1), "r"(a2), "r"(a3),
                      "r"(bfr[q][nt][0]), "r"(bfr[q][nt][1]));
            }
        }

        // ---- reduce dots over tig lanes; publish (col-group 0 only) ----
        pd0 += __shfl_xor_sync(0xffffffffu, pd0, 1);
        pd0 += __shfl_xor_sync(0xffffffffu, pd0, 2);
        pd1 += __shfl_xor_sync(0xffffffffu, pd1, 1);
        pd1 += __shfl_xor_sync(0xffffffffu, pd1, 2);
        if (cg == 0 && tig == 0) {
            sdots[rA] = pd0;
            sdots[rB] = pd1;
        }
        __syncthreads();   // sdots complete

        // ---- warp-local softmax over rows 1..63 ----
        float x0 = (lane >= 1) ? sdots[lane] : -1e30f;
        float x1 = sdots[lane + 32];
        float m = fmaxf(x0, x1);
#pragma unroll
        for (int off = 16; off; off >>= 1)
            m = fmaxf(m, __shfl_xor_sync(0xffffffffu, m, off));
        float e0s = (lane >= 1) ? __expf(x0 - m) : 0.f;
        float e1s = __expf(x1 - m);
        float s = e0s + e1s;
#pragma unroll
        for (int off = 16; off; off >>= 1)
            s += __shfl_xor_sync(0xffffffffu, s, off);
        const float inv = 1.f / s;

        const float fA = (rA == 0) ? 1.f : __expf(pd0 - m) * inv;
        const float fB = __expf(pd1 - m) * inv;   // rB >= 8, never robot

        // ---- epilogue: scale, elu, STG.128 (N-perm makes cols contiguous) ----
        float* ob = out + base + (size_t)g * 4096;
#pragma unroll
        for (int p = 0; p < 2; ++p) {
            const int col = cg * 32 + p * 16 + tig * 4;
            float4 v0 = make_float4(elu1(acc[2 * p][0] * fA),
                                    elu1(acc[2 * p][1] * fA),
                                    elu1(acc[2 * p + 1][0] * fA),
                                    elu1(acc[2 * p + 1][1] * fA));
            float4 v1 = make_float4(elu1(acc[2 * p][2] * fB),
                                    elu1(acc[2 * p][3] * fB),
                                    elu1(acc[2 * p + 1][2] * fB),
                                    elu1(acc[2 * p + 1][3] * fB));
            *reinterpret_cast<float4*>(ob + rA * 64 + col) = v0;
            *reinterpret_cast<float4*>(ob + rB * 64 + col) = v1;
        }
    }
}

extern "C" void kernel_launch(void* const* d_in, const int* in_sizes, int n_in,
                              void* d_out, int out_size) {
    const float* h = (const float*)d_in[0];   // (16384, 64, 64) f32
    const float* W = (const float*)d_in[1];   // (64, 64) f32
    const float* a = (const float*)d_in[2];   // (128, 1) f32
    float* out = (float*)d_out;               // (16384, 64, 64) f32

    gat_fused_kernel<<<16384 / GB, 256>>>(h, W, a, out);
}